// round 2
// baseline (speedup 1.0000x reference)
#include <cuda_runtime.h>
#include <math.h>

// Problem constants
#define NTOK 200704          // 64*56*56
#define QKVD 768
#define CDIM 256

// Scratch (device globals: allocation-free rule)
__device__ float g_qkv[(size_t)NTOK * QKVD];   // 616 MB
__device__ float g_att[(size_t)NTOK * CDIM];   // 205 MB

// ---------------------------------------------------------------------------
// Register-blocked fp32 GEMM with bias: C[M,N] = A[M,K] @ B[K,N] + bias[N]
// BM=BN=64, BK=16, 256 threads, 4x4 per thread. M%64==0, N%64==0, K%16==0.
// ---------------------------------------------------------------------------
template <int BM, int BN, int BK>
__global__ void __launch_bounds__(256) gemm_bias(
    const float* __restrict__ A, const float* __restrict__ Bw,
    const float* __restrict__ bias, float* __restrict__ C,
    int M, int N, int K) {
  __shared__ float As[BK][BM];
  __shared__ float Bs[BK][BN];
  const int tid = threadIdx.x;
  const int bm = blockIdx.y * BM;
  const int bn = blockIdx.x * BN;
  const int tx = tid & 15;          // 0..15 -> N micro
  const int ty = tid >> 4;          // 0..15 -> M micro
  const int arow = tid >> 2;        // 0..63
  const int acol = (tid & 3) << 2;  // 0..12
  const int brow = tid >> 4;        // 0..15
  const int bcol = (tid & 15) << 2; // 0..60

  float acc[4][4] = {};

  for (int k0 = 0; k0 < K; k0 += BK) {
    float4 av = *reinterpret_cast<const float4*>(
        &A[(size_t)(bm + arow) * K + k0 + acol]);
    As[acol + 0][arow] = av.x;
    As[acol + 1][arow] = av.y;
    As[acol + 2][arow] = av.z;
    As[acol + 3][arow] = av.w;
    *reinterpret_cast<float4*>(&Bs[brow][bcol]) =
        *reinterpret_cast<const float4*>(
            &Bw[(size_t)(k0 + brow) * N + bn + bcol]);
    __syncthreads();
#pragma unroll
    for (int k = 0; k < BK; ++k) {
      float4 ra = *reinterpret_cast<const float4*>(&As[k][ty * 4]);
      float4 rb = *reinterpret_cast<const float4*>(&Bs[k][tx * 4]);
      float a[4] = {ra.x, ra.y, ra.z, ra.w};
      float b[4] = {rb.x, rb.y, rb.z, rb.w};
#pragma unroll
      for (int i = 0; i < 4; ++i)
#pragma unroll
        for (int j = 0; j < 4; ++j) acc[i][j] += a[i] * b[j];
    }
    __syncthreads();
  }

#pragma unroll
  for (int i = 0; i < 4; ++i) {
    float4 o;
    o.x = acc[i][0] + bias[bn + tx * 4 + 0];
    o.y = acc[i][1] + bias[bn + tx * 4 + 1];
    o.z = acc[i][2] + bias[bn + tx * 4 + 2];
    o.w = acc[i][3] + bias[bn + tx * 4 + 3];
    *reinterpret_cast<float4*>(
        &C[(size_t)(bm + ty * 4 + i) * N + bn + tx * 4]) = o;
  }
}

// ---------------------------------------------------------------------------
// Windowed attention. One CTA per (window, head). 128 threads.
// q,k,v: 49x32 (padded 33 to avoid LDS bank conflicts).
// score = (q.kT)*sqrt(32) + pos[(rk+ck)][(rl+cl)]; softmax over l; out = p@v.
// ---------------------------------------------------------------------------
__global__ void __launch_bounds__(128) win_attn(const float* __restrict__ pos) {
  __shared__ float sq[49][33];
  __shared__ float sk[49][33];
  __shared__ float sv[49][33];
  __shared__ float ss[49 * 49];
  __shared__ float sp[169];

  const int tid = threadIdx.x;
  const int win = blockIdx.x;      // 0..4095
  const int head = blockIdx.y;     // 0..7
  const int b = win >> 6;
  const int wi = (win >> 3) & 7;
  const int wj = win & 7;
  // global row index of window origin in the [B,56,56] token grid
  const long rowbase = ((long)(b * 56 + wi * 7)) * 56 + wj * 7;

  for (int i = tid; i < 169; i += 128) sp[i] = pos[i];
  for (int i = tid; i < 49 * 32; i += 128) {
    const int t = i >> 5, d = i & 31;
    const long grow = rowbase + (t / 7) * 56 + (t % 7);
    const float* p = &g_qkv[grow * 768 + head * 32 + d];
    sq[t][d] = p[0];
    sk[t][d] = p[256];
    sv[t][d] = p[512];
  }
  __syncthreads();

  const float scale = 5.656854249492380195f;  // sqrt(32) (reference MULTIPLIES)
  for (int p = tid; p < 49 * 49; p += 128) {
    const int i = p / 49, j = p % 49;
    float acc = 0.f;
#pragma unroll
    for (int d = 0; d < 32; ++d) acc += sq[i][d] * sk[j][d];
    const int bi = (i / 7) + (i % 7);
    const int bj = (j / 7) + (j % 7);
    ss[p] = acc * scale + sp[bi * 13 + bj];
  }
  __syncthreads();

  // softmax: 4 warps, strided rows
  const int warp = tid >> 5, lane = tid & 31;
  for (int r = warp; r < 49; r += 4) {
    float v0 = ss[r * 49 + lane];
    float v1 = (lane + 32 < 49) ? ss[r * 49 + lane + 32] : -INFINITY;
    float m = fmaxf(v0, v1);
#pragma unroll
    for (int o = 16; o; o >>= 1) m = fmaxf(m, __shfl_xor_sync(~0u, m, o));
    float e0 = expf(v0 - m);
    float e1 = (lane + 32 < 49) ? expf(v1 - m) : 0.f;
    float sum = e0 + e1;
#pragma unroll
    for (int o = 16; o; o >>= 1) sum += __shfl_xor_sync(~0u, sum, o);
    const float inv = 1.f / sum;
    ss[r * 49 + lane] = e0 * inv;
    if (lane + 32 < 49) ss[r * 49 + lane + 32] = e1 * inv;
  }
  __syncthreads();

  for (int p = tid; p < 49 * 32; p += 128) {
    const int i = p >> 5, d = p & 31;
    float acc = 0.f;
#pragma unroll
    for (int l = 0; l < 49; ++l) acc += ss[i * 49 + l] * sv[l][d];
    const long grow = rowbase + (i / 7) * 56 + (i % 7);
    g_att[grow * 256 + head * 32 + d] = acc;
  }
}

// ---------------------------------------------------------------------------
extern "C" void kernel_launch(void* const* d_in, const int* in_sizes, int n_in,
                              void* d_out, int out_size) {
  const float* x     = (const float*)d_in[0];
  const float* pos   = (const float*)d_in[1];
  const float* w_qkv = (const float*)d_in[2];
  const float* b_qkv = (const float*)d_in[3];
  const float* w_out = (const float*)d_in[4];
  const float* b_out = (const float*)d_in[5];
  float* out = (float*)d_out;

  float* qkv_p = nullptr;
  float* att_p = nullptr;
  cudaGetSymbolAddress((void**)&qkv_p, g_qkv);
  cudaGetSymbolAddress((void**)&att_p, g_att);

  // 1) qkv = x @ w_qkv + b_qkv   [200704 x 768]
  dim3 g1(QKVD / 64, NTOK / 64);
  gemm_bias<64, 64, 16><<<g1, 256>>>(x, w_qkv, b_qkv, qkv_p, NTOK, QKVD, CDIM);

  // 2) windowed attention -> g_att [200704 x 256]
  dim3 g2(4096, 8);
  win_attn<<<g2, 128>>>(pos);

  // 3) out = att @ w_out + b_out  [200704 x 256]
  dim3 g3(CDIM / 64, NTOK / 64);
  gemm_bias<64, 64, 16><<<g3, 256>>>(att_p, w_out, b_out, out, NTOK, CDIM, CDIM);
}

// round 7
// speedup vs baseline: 1.9119x; 1.9119x over previous
#include <cuda_runtime.h>
#include <cuda_bf16.h>
#include <math.h>

#define NTOK 200704          // 64*56*56
#define QKVD 768
#define CDIM 256

// ------------------------- device scratch (no allocs allowed) --------------
__device__ float          g_qkv[(size_t)NTOK * QKVD];   // fp32 qkv for attention
__device__ __nv_bfloat16  g_xh[(size_t)NTOK * CDIM];    // x split hi
__device__ __nv_bfloat16  g_xl[(size_t)NTOK * CDIM];    // x split lo
__device__ __nv_bfloat16  g_ath[(size_t)NTOK * CDIM];   // attention out hi
__device__ __nv_bfloat16  g_atl[(size_t)NTOK * CDIM];   // attention out lo
__device__ __nv_bfloat16  g_wqh[(size_t)QKVD * CDIM];   // w_qkv^T split hi  [N][K]
__device__ __nv_bfloat16  g_wql[(size_t)QKVD * CDIM];
__device__ __nv_bfloat16  g_woh[(size_t)CDIM * CDIM];   // w_out^T split hi  [N][K]
__device__ __nv_bfloat16  g_wol[(size_t)CDIM * CDIM];

// ------------------------- helpers -----------------------------------------
__device__ __forceinline__ unsigned su32(const void* p) {
  return (unsigned)__cvta_generic_to_shared(p);
}
__device__ __forceinline__ void cp16(unsigned s, const void* g) {
  asm volatile("cp.async.cg.shared.global [%0], [%1], 16;\n" ::"r"(s), "l"(g));
}
__device__ __forceinline__ void cp_commit() {
  asm volatile("cp.async.commit_group;\n");
}
template <int N>
__device__ __forceinline__ void cp_wait() {
  asm volatile("cp.async.wait_group %0;\n" ::"n"(N));
}
__device__ __forceinline__ void ldm4(unsigned a, unsigned& r0, unsigned& r1,
                                     unsigned& r2, unsigned& r3) {
  asm volatile(
      "ldmatrix.sync.aligned.m8n8.x4.shared.b16 {%0,%1,%2,%3}, [%4];\n"
      : "=r"(r0), "=r"(r1), "=r"(r2), "=r"(r3)
      : "r"(a));
}
__device__ __forceinline__ void mma16816(float* c, const unsigned* a,
                                         unsigned b0, unsigned b1) {
  asm volatile(
      "mma.sync.aligned.m16n8k16.row.col.f32.bf16.bf16.f32 "
      "{%0,%1,%2,%3},{%4,%5,%6,%7},{%8,%9},{%0,%1,%2,%3};\n"
      : "+f"(c[0]), "+f"(c[1]), "+f"(c[2]), "+f"(c[3])
      : "r"(a[0]), "r"(a[1]), "r"(a[2]), "r"(a[3]), "r"(b0), "r"(b1));
}
__device__ __forceinline__ void split1(float v, __nv_bfloat16& h,
                                       __nv_bfloat16& l) {
  h = __float2bfloat16(v);
  l = __float2bfloat16(v - __bfloat162float(h));
}

// ------------------------- split kernels ------------------------------------
__global__ void split_act(const float* __restrict__ in,
                          __nv_bfloat16* __restrict__ h,
                          __nv_bfloat16* __restrict__ l, size_t n4) {
  size_t i = (size_t)blockIdx.x * blockDim.x + threadIdx.x;
  if (i >= n4) return;
  float4 v = reinterpret_cast<const float4*>(in)[i];
  __nv_bfloat16 h0, h1, h2, h3, l0, l1, l2, l3;
  split1(v.x, h0, l0); split1(v.y, h1, l1);
  split1(v.z, h2, l2); split1(v.w, h3, l3);
  __nv_bfloat162* hp = reinterpret_cast<__nv_bfloat162*>(h) + 2 * i;
  __nv_bfloat162* lp = reinterpret_cast<__nv_bfloat162*>(l) + 2 * i;
  hp[0] = __nv_bfloat162(h0, h1); hp[1] = __nv_bfloat162(h2, h3);
  lp[0] = __nv_bfloat162(l0, l1); lp[1] = __nv_bfloat162(l2, l3);
}

// w[K][N] row-major -> h/l[N][K] (k contiguous)
__global__ void split_wT(const float* __restrict__ w,
                         __nv_bfloat16* __restrict__ h,
                         __nv_bfloat16* __restrict__ l, int K, int N) {
  int idx = blockIdx.x * 256 + threadIdx.x;
  if (idx >= K * N) return;
  int n = idx / K, k = idx - n * K;
  float v = w[(size_t)k * N + n];
  __nv_bfloat16 hh, ll;
  split1(v, hh, ll);
  h[idx] = hh; l[idx] = ll;
}

// ------------------------- split-bf16 tensor-core GEMM ----------------------
// C[M,N] = A[M,K] @ B[N,K]^T + bias, A/B given as bf16 (hi,lo) planes.
// CTA tile 128x128, BK=32, 256 threads (8 warps of 64x32), double-buffered.
#define LDAB 40          // smem row stride in bf16 elems (80B, conflict-free)
#define PLANE_B (128 * LDAB * 2)        // 10240 bytes per plane
#define STAGE_B (4 * PLANE_B)           // 40960 bytes per stage

__global__ void __launch_bounds__(256) gemm_split(
    const __nv_bfloat16* __restrict__ Ah, const __nv_bfloat16* __restrict__ Al,
    const __nv_bfloat16* __restrict__ Bh, const __nv_bfloat16* __restrict__ Bl,
    const float* __restrict__ bias, float* __restrict__ C, int M, int N,
    int K) {
  extern __shared__ __align__(16) char smem[];
  const unsigned sbase = su32(smem);
  const int tid = threadIdx.x;
  const int lane = tid & 31;
  const int warp = tid >> 5;
  const int wm = warp & 1;        // 2 m sub-tiles of 64
  const int wn = warp >> 1;       // 4 n sub-tiles of 32
  const int bm = blockIdx.y * 128;
  const int bn = blockIdx.x * 128;

  const __nv_bfloat16* gsrc[4] = {Ah + (size_t)bm * K, Al + (size_t)bm * K,
                                  Bh + (size_t)bn * K, Bl + (size_t)bn * K};

  float acc[4][4][4];
#pragma unroll
  for (int i = 0; i < 4; ++i)
#pragma unroll
    for (int j = 0; j < 4; ++j)
#pragma unroll
      for (int r = 0; r < 4; ++r) acc[i][j][r] = 0.f;

  const int NK = K >> 5;  // BK = 32

  auto load_stage = [&](int it, int buf) {
    const int k0 = it << 5;
    const unsigned sb = sbase + buf * STAGE_B;
#pragma unroll
    for (int a = 0; a < 4; ++a) {
      const __nv_bfloat16* g = gsrc[a];
#pragma unroll
      for (int w = 0; w < 2; ++w) {
        int chunk = tid + (w << 8);
        int row = chunk >> 2, kc = chunk & 3;
        cp16(sb + a * PLANE_B + row * 80 + kc * 16,
             g + (size_t)row * K + k0 + kc * 8);
      }
    }
  };

  load_stage(0, 0);
  cp_commit();

  for (int it = 0; it < NK; ++it) {
    const int buf = it & 1;
    if (it + 1 < NK) {
      load_stage(it + 1, buf ^ 1);
      cp_commit();
      cp_wait<1>();
    } else {
      cp_wait<0>();
    }
    __syncthreads();

    const unsigned sb = sbase + buf * STAGE_B;
#pragma unroll
    for (int kc = 0; kc < 2; ++kc) {
      // B fragments: 2 pairs of n8 tiles x (hi,lo)
      unsigned bh[2][4], bl[2][4];
      const int grp = lane >> 3;
      const int nrow0 = wn * 32 + ((grp >> 1) << 3) + (lane & 7);
      const int kk = (kc << 4) + ((grp & 1) << 3);
#pragma unroll
      for (int p = 0; p < 2; ++p) {
        const unsigned off = (nrow0 + (p << 4)) * 80 + kk * 2;
        ldm4(sb + 2 * PLANE_B + off, bh[p][0], bh[p][1], bh[p][2], bh[p][3]);
        ldm4(sb + 3 * PLANE_B + off, bl[p][0], bl[p][1], bl[p][2], bl[p][3]);
      }
      const int ar = wm * 64 + (lane & 15);
      const int acol = (kc << 4) + ((lane >> 4) << 3);
#pragma unroll
      for (int mt = 0; mt < 4; ++mt) {
        unsigned ah[4], al[4];
        const unsigned aoff = (ar + (mt << 4)) * 80 + acol * 2;
        ldm4(sb + aoff, ah[0], ah[1], ah[2], ah[3]);
        ldm4(sb + PLANE_B + aoff, al[0], al[1], al[2], al[3]);
#pragma unroll
        for (int nt = 0; nt < 4; ++nt) {
          unsigned b0h = bh[nt >> 1][(nt & 1) * 2], b1h = bh[nt >> 1][(nt & 1) * 2 + 1];
          unsigned b0l = bl[nt >> 1][(nt & 1) * 2], b1l = bl[nt >> 1][(nt & 1) * 2 + 1];
          mma16816(acc[mt][nt], ah, b0h, b1h);   // hi*hi
          mma16816(acc[mt][nt], ah, b0l, b1l);   // hi*lo
          mma16816(acc[mt][nt], al, b0h, b1h);   // lo*hi
        }
      }
    }
    __syncthreads();
  }

  // epilogue
#pragma unroll
  for (int mt = 0; mt < 4; ++mt) {
    const int row = bm + wm * 64 + mt * 16 + (lane >> 2);
#pragma unroll
    for (int nt = 0; nt < 4; ++nt) {
      const int col = bn + wn * 32 + nt * 8 + (lane & 3) * 2;
      const float b0 = bias[col], b1 = bias[col + 1];
      float2 o0 = {acc[mt][nt][0] + b0, acc[mt][nt][1] + b1};
      float2 o1 = {acc[mt][nt][2] + b0, acc[mt][nt][3] + b1};
      *reinterpret_cast<float2*>(&C[(size_t)row * N + col]) = o0;
      *reinterpret_cast<float2*>(&C[(size_t)(row + 8) * N + col]) = o1;
    }
  }
}

// ------------------------- windowed attention -------------------------------
__global__ void __launch_bounds__(128) win_attn(const float* __restrict__ pos) {
  __shared__ float sq[49][33];
  __shared__ float sk[49][33];
  __shared__ float sv[49][33];
  __shared__ float ss[49 * 49];
  __shared__ float sp[169];

  const int tid = threadIdx.x;
  const int win = blockIdx.x;
  const int head = blockIdx.y;
  const int b = win >> 6;
  const int wi = (win >> 3) & 7;
  const int wj = win & 7;
  const long rowbase = ((long)(b * 56 + wi * 7)) * 56 + wj * 7;

  for (int i = tid; i < 169; i += 128) sp[i] = pos[i];
  for (int i = tid; i < 49 * 32; i += 128) {
    const int t = i >> 5, d = i & 31;
    const long grow = rowbase + (t / 7) * 56 + (t % 7);
    const float* p = &g_qkv[grow * 768 + head * 32 + d];
    sq[t][d] = p[0];
    sk[t][d] = p[256];
    sv[t][d] = p[512];
  }
  __syncthreads();

  const float scale = 5.656854249492380195f;  // sqrt(32), reference multiplies
  for (int p = tid; p < 49 * 49; p += 128) {
    const int i = p / 49, j = p % 49;
    float acc = 0.f;
#pragma unroll
    for (int d = 0; d < 32; ++d) acc += sq[i][d] * sk[j][d];
    const int bi = (i / 7) + (i % 7);
    const int bj = (j / 7) + (j % 7);
    ss[p] = acc * scale + sp[bi * 13 + bj];
  }
  __syncthreads();

  const int warp = tid >> 5, lane = tid & 31;
  for (int r = warp; r < 49; r += 4) {
    float v0 = ss[r * 49 + lane];
    float v1 = (lane + 32 < 49) ? ss[r * 49 + lane + 32] : -INFINITY;
    float m = fmaxf(v0, v1);
#pragma unroll
    for (int o = 16; o; o >>= 1) m = fmaxf(m, __shfl_xor_sync(~0u, m, o));
    float e0 = expf(v0 - m);
    float e1 = (lane + 32 < 49) ? expf(v1 - m) : 0.f;
    float sum = e0 + e1;
#pragma unroll
    for (int o = 16; o; o >>= 1) sum += __shfl_xor_sync(~0u, sum, o);
    const float inv = 1.f / sum;
    ss[r * 49 + lane] = e0 * inv;
    if (lane + 32 < 49) ss[r * 49 + lane + 32] = e1 * inv;
  }
  __syncthreads();

  for (int p = tid; p < 49 * 32; p += 128) {
    const int i = p >> 5, d = p & 31;
    float acc = 0.f;
#pragma unroll
    for (int l = 0; l < 49; ++l) acc += ss[i * 49 + l] * sv[l][d];
    const long grow = rowbase + (i / 7) * 56 + (i % 7);
    __nv_bfloat16 hh, ll;
    split1(acc, hh, ll);
    g_ath[grow * 256 + head * 32 + d] = hh;
    g_atl[grow * 256 + head * 32 + d] = ll;
  }
}

// ---------------------------------------------------------------------------
extern "C" void kernel_launch(void* const* d_in, const int* in_sizes, int n_in,
                              void* d_out, int out_size) {
  const float* x     = (const float*)d_in[0];
  const float* pos   = (const float*)d_in[1];
  const float* w_qkv = (const float*)d_in[2];
  const float* b_qkv = (const float*)d_in[3];
  const float* w_out = (const float*)d_in[4];
  const float* b_out = (const float*)d_in[5];
  float* out = (float*)d_out;

  float* qkv_p; __nv_bfloat16 *xh, *xl, *ath, *atl, *wqh, *wql, *woh, *wol;
  cudaGetSymbolAddress((void**)&qkv_p, g_qkv);
  cudaGetSymbolAddress((void**)&xh, g_xh);
  cudaGetSymbolAddress((void**)&xl, g_xl);
  cudaGetSymbolAddress((void**)&ath, g_ath);
  cudaGetSymbolAddress((void**)&atl, g_atl);
  cudaGetSymbolAddress((void**)&wqh, g_wqh);
  cudaGetSymbolAddress((void**)&wql, g_wql);
  cudaGetSymbolAddress((void**)&woh, g_woh);
  cudaGetSymbolAddress((void**)&wol, g_wol);

  static bool attr_set = false;
  if (!attr_set) {
    cudaFuncSetAttribute(gemm_split, cudaFuncAttributeMaxDynamicSharedMemorySize,
                         2 * STAGE_B);
    attr_set = true;
  }

  // 0) split inputs to bf16 hi/lo planes
  {
    size_t n4 = (size_t)NTOK * CDIM / 4;
    split_act<<<(unsigned)((n4 + 255) / 256), 256>>>(x, xh, xl, n4);
    split_wT<<<(CDIM * QKVD + 255) / 256, 256>>>(w_qkv, wqh, wql, CDIM, QKVD);
    split_wT<<<(CDIM * CDIM + 255) / 256, 256>>>(w_out, woh, wol, CDIM, CDIM);
  }

  // 1) qkv = x @ w_qkv + b_qkv  [200704 x 768]
  {
    dim3 g(QKVD / 128, NTOK / 128);
    gemm_split<<<g, 256, 2 * STAGE_B>>>(xh, xl, wqh, wql, b_qkv, qkv_p,
                                        NTOK, QKVD, CDIM);
  }

  // 2) windowed attention -> att hi/lo planes
  {
    dim3 g(4096, 8);
    win_attn<<<g, 128>>>(pos);
  }

  // 3) out = att @ w_out + b_out  [200704 x 256]
  {
    dim3 g(CDIM / 128, NTOK / 128);
    gemm_split<<<g, 256, 2 * STAGE_B>>>(ath, atl, woh, wol, b_out, out,
                                        NTOK, CDIM, CDIM);
  }
}

// round 8
// speedup vs baseline: 2.5093x; 1.3125x over previous
#include <cuda_runtime.h>
#include <cuda_bf16.h>
#include <math.h>

#define NTOK 200704          // 64*56*56
#define QKVD 768
#define CDIM 256

// ------------------------- device scratch (no allocs allowed) --------------
__device__ float          g_qkv[(size_t)NTOK * QKVD];   // fp32 qkv for attention
__device__ __nv_bfloat16  g_xh[(size_t)NTOK * CDIM];    // x split hi
__device__ __nv_bfloat16  g_xl[(size_t)NTOK * CDIM];    // x split lo
__device__ __nv_bfloat16  g_ath[(size_t)NTOK * CDIM];   // attention out hi
__device__ __nv_bfloat16  g_atl[(size_t)NTOK * CDIM];   // attention out lo
__device__ __nv_bfloat16  g_wqh[(size_t)QKVD * CDIM];   // w_qkv^T split hi  [N][K]
__device__ __nv_bfloat16  g_wql[(size_t)QKVD * CDIM];
__device__ __nv_bfloat16  g_woh[(size_t)CDIM * CDIM];   // w_out^T split hi  [N][K]
__device__ __nv_bfloat16  g_wol[(size_t)CDIM * CDIM];

// ------------------------- helpers -----------------------------------------
__device__ __forceinline__ unsigned su32(const void* p) {
  return (unsigned)__cvta_generic_to_shared(p);
}
__device__ __forceinline__ void cp16(unsigned s, const void* g) {
  asm volatile("cp.async.cg.shared.global [%0], [%1], 16;\n" ::"r"(s), "l"(g));
}
__device__ __forceinline__ void cp_commit() {
  asm volatile("cp.async.commit_group;\n");
}
template <int N>
__device__ __forceinline__ void cp_wait() {
  asm volatile("cp.async.wait_group %0;\n" ::"n"(N));
}
__device__ __forceinline__ void ldm4(unsigned a, unsigned& r0, unsigned& r1,
                                     unsigned& r2, unsigned& r3) {
  asm volatile(
      "ldmatrix.sync.aligned.m8n8.x4.shared.b16 {%0,%1,%2,%3}, [%4];\n"
      : "=r"(r0), "=r"(r1), "=r"(r2), "=r"(r3)
      : "r"(a));
}
__device__ __forceinline__ void mma16816(float* c, const unsigned* a,
                                         unsigned b0, unsigned b1) {
  asm volatile(
      "mma.sync.aligned.m16n8k16.row.col.f32.bf16.bf16.f32 "
      "{%0,%1,%2,%3},{%4,%5,%6,%7},{%8,%9},{%0,%1,%2,%3};\n"
      : "+f"(c[0]), "+f"(c[1]), "+f"(c[2]), "+f"(c[3])
      : "r"(a[0]), "r"(a[1]), "r"(a[2]), "r"(a[3]), "r"(b0), "r"(b1));
}
__device__ __forceinline__ void split1(float v, __nv_bfloat16& h,
                                       __nv_bfloat16& l) {
  h = __float2bfloat16(v);
  l = __float2bfloat16(v - __bfloat162float(h));
}

// ------------------------- split kernels ------------------------------------
__global__ void split_act(const float* __restrict__ in,
                          __nv_bfloat16* __restrict__ h,
                          __nv_bfloat16* __restrict__ l, size_t n4) {
  size_t i = (size_t)blockIdx.x * blockDim.x + threadIdx.x;
  if (i >= n4) return;
  float4 v = reinterpret_cast<const float4*>(in)[i];
  __nv_bfloat16 h0, h1, h2, h3, l0, l1, l2, l3;
  split1(v.x, h0, l0); split1(v.y, h1, l1);
  split1(v.z, h2, l2); split1(v.w, h3, l3);
  __nv_bfloat162* hp = reinterpret_cast<__nv_bfloat162*>(h) + 2 * i;
  __nv_bfloat162* lp = reinterpret_cast<__nv_bfloat162*>(l) + 2 * i;
  hp[0] = __nv_bfloat162(h0, h1); hp[1] = __nv_bfloat162(h2, h3);
  lp[0] = __nv_bfloat162(l0, l1); lp[1] = __nv_bfloat162(l2, l3);
}

// w[K][N] row-major -> h/l[N][K] (k contiguous)
__global__ void split_wT(const float* __restrict__ w,
                         __nv_bfloat16* __restrict__ h,
                         __nv_bfloat16* __restrict__ l, int K, int N) {
  int idx = blockIdx.x * 256 + threadIdx.x;
  if (idx >= K * N) return;
  int n = idx / K, k = idx - n * K;
  float v = w[(size_t)k * N + n];
  __nv_bfloat16 hh, ll;
  split1(v, hh, ll);
  h[idx] = hh; l[idx] = ll;
}

// ------------------------- split-bf16 tensor-core GEMM ----------------------
// C[M,N] = A[M,K] @ B[N,K]^T + bias, A/B as bf16 (hi,lo) planes.
// CTA 128x128, BK=32, 256 threads (8 warps of 64x32), 3-stage cp.async pipe.
// Smem: 64B rows with slot swizzle (chunk ^ ((row>>1)&3)) -> 8 consecutive
// ldmatrix rows hit 8 distinct 16B granules (conflict-free).
#define PLANE_B (128 * 64)              // 8192 bytes per plane
#define STAGE_B (4 * PLANE_B)           // 32768 bytes per stage
#define NSTAGE 3

__device__ __forceinline__ unsigned swz(int row, int chunk) {
  return (unsigned)(row * 64 + ((chunk ^ ((row >> 1) & 3)) << 4));
}

__global__ void __launch_bounds__(256) gemm_split(
    const __nv_bfloat16* __restrict__ Ah, const __nv_bfloat16* __restrict__ Al,
    const __nv_bfloat16* __restrict__ Bh, const __nv_bfloat16* __restrict__ Bl,
    const float* __restrict__ bias, float* __restrict__ C, int M, int N,
    int K) {
  extern __shared__ __align__(16) char smem[];
  const unsigned sbase = su32(smem);
  const int tid = threadIdx.x;
  const int lane = tid & 31;
  const int warp = tid >> 5;
  const int wm = warp & 1;        // 2 m sub-tiles of 64
  const int wn = warp >> 1;       // 4 n sub-tiles of 32
  const int bm = blockIdx.y * 128;
  const int bn = blockIdx.x * 128;

  const __nv_bfloat16* gsrc[4] = {Ah + (size_t)bm * K, Al + (size_t)bm * K,
                                  Bh + (size_t)bn * K, Bl + (size_t)bn * K};

  float acc[4][4][4];
#pragma unroll
  for (int i = 0; i < 4; ++i)
#pragma unroll
    for (int j = 0; j < 4; ++j)
#pragma unroll
      for (int r = 0; r < 4; ++r) acc[i][j][r] = 0.f;

  const int NK = K >> 5;  // BK = 32

  auto load_stage = [&](int it, int buf) {
    const int k0 = it << 5;
    const unsigned sb = sbase + buf * STAGE_B;
#pragma unroll
    for (int a = 0; a < 4; ++a) {
      const __nv_bfloat16* g = gsrc[a];
#pragma unroll
      for (int w = 0; w < 2; ++w) {
        int chunk = tid + (w << 8);
        int row = chunk >> 2, kc = chunk & 3;
        cp16(sb + a * PLANE_B + swz(row, kc),
             g + (size_t)row * K + k0 + kc * 8);
      }
    }
  };

  load_stage(0, 0);
  cp_commit();
  load_stage(1, 1);
  cp_commit();

  for (int it = 0; it < NK; ++it) {
    const int buf = it % NSTAGE;
    if (it >= NK - 2) {
      cp_wait<0>();
    } else {
      cp_wait<1>();
    }
    __syncthreads();

    const unsigned sb = sbase + buf * STAGE_B;
#pragma unroll
    for (int kc = 0; kc < 2; ++kc) {
      unsigned bh[2][4], bl[2][4];
      const int grp = lane >> 3;
      const int nrow0 = wn * 32 + ((grp >> 1) << 3) + (lane & 7);
      const int chunkB = (kc << 1) + (grp & 1);
#pragma unroll
      for (int p = 0; p < 2; ++p) {
        const unsigned off = swz(nrow0 + (p << 4), chunkB);
        ldm4(sb + 2 * PLANE_B + off, bh[p][0], bh[p][1], bh[p][2], bh[p][3]);
        ldm4(sb + 3 * PLANE_B + off, bl[p][0], bl[p][1], bl[p][2], bl[p][3]);
      }
      const int ar = wm * 64 + (lane & 15);
      const int chunkA = (kc << 1) + (lane >> 4);
#pragma unroll
      for (int mt = 0; mt < 4; ++mt) {
        unsigned ah[4], al[4];
        const unsigned aoff = swz(ar + (mt << 4), chunkA);
        ldm4(sb + aoff, ah[0], ah[1], ah[2], ah[3]);
        ldm4(sb + PLANE_B + aoff, al[0], al[1], al[2], al[3]);
#pragma unroll
        for (int nt = 0; nt < 4; ++nt) {
          unsigned b0h = bh[nt >> 1][(nt & 1) * 2], b1h = bh[nt >> 1][(nt & 1) * 2 + 1];
          unsigned b0l = bl[nt >> 1][(nt & 1) * 2], b1l = bl[nt >> 1][(nt & 1) * 2 + 1];
          mma16816(acc[mt][nt], ah, b0h, b1h);   // hi*hi
          mma16816(acc[mt][nt], ah, b0l, b1l);   // hi*lo
          mma16816(acc[mt][nt], al, b0h, b1h);   // lo*hi
        }
      }
    }

    if (it + 2 < NK) {
      load_stage(it + 2, (it + 2) % NSTAGE);
      cp_commit();
    }
  }

  // epilogue
#pragma unroll
  for (int mt = 0; mt < 4; ++mt) {
    const int row = bm + wm * 64 + mt * 16 + (lane >> 2);
#pragma unroll
    for (int nt = 0; nt < 4; ++nt) {
      const int col = bn + wn * 32 + nt * 8 + (lane & 3) * 2;
      const float b0 = bias[col], b1 = bias[col + 1];
      float2 o0 = {acc[mt][nt][0] + b0, acc[mt][nt][1] + b1};
      float2 o1 = {acc[mt][nt][2] + b0, acc[mt][nt][3] + b1};
      *reinterpret_cast<float2*>(&C[(size_t)row * N + col]) = o0;
      *reinterpret_cast<float2*>(&C[(size_t)(row + 8) * N + col]) = o1;
    }
  }
}

// ------------------------- windowed attention (register-tiled) --------------
// One CTA per (window, head), 128 threads. 4x4 register tiles in both the
// QK^T phase (13x13=169 tiles over 52x52-padded score) and the PV phase
// (13x8=104 tiles over 52x32-padded out). LDS per FMA drops 2.0 -> 0.5.
__global__ void __launch_bounds__(128) win_attn(const float* __restrict__ pos) {
  __shared__ float sq[52][33];
  __shared__ float sk[52][33];
  __shared__ float sv[49][33];
  __shared__ float ss[52 * 49];
  __shared__ float sp[169];

  const int tid = threadIdx.x;
  const int win = blockIdx.x;
  const int head = blockIdx.y;
  const int b = win >> 6;
  const int wi = (win >> 3) & 7;
  const int wj = win & 7;
  const long rowbase = ((long)(b * 56 + wi * 7)) * 56 + wj * 7;

  for (int i = tid; i < 169; i += 128) sp[i] = pos[i];
  // zero the 3 pad rows of sq/sk (rows 49..51)
  if (tid < 99) {
    int r = 49 + tid / 33, c = tid % 33;
    sq[r][c] = 0.f;
    sk[r][c] = 0.f;
  }
  for (int i = tid; i < 49 * 32; i += 128) {
    const int t = i >> 5, d = i & 31;
    const long grow = rowbase + (t / 7) * 56 + (t % 7);
    const float* p = &g_qkv[grow * 768 + head * 32 + d];
    sq[t][d] = p[0];
    sk[t][d] = p[256];
    sv[t][d] = p[512];
  }
  __syncthreads();

  const float scale = 5.656854249492380195f;  // sqrt(32), reference multiplies

  // ---- score: 169 tiles of 4x4 ----
  for (int t = tid; t < 169; t += 128) {
    const int ti = t / 13, tj = t - ti * 13;
    const int i0 = ti * 4, j0 = tj * 4;
    float acc[4][4] = {};
#pragma unroll
    for (int d = 0; d < 32; ++d) {
      float a0 = sq[i0 + 0][d], a1 = sq[i0 + 1][d];
      float a2 = sq[i0 + 2][d], a3 = sq[i0 + 3][d];
      float b0 = sk[j0 + 0][d], b1 = sk[j0 + 1][d];
      float b2 = sk[j0 + 2][d], b3 = sk[j0 + 3][d];
      acc[0][0] += a0 * b0; acc[0][1] += a0 * b1; acc[0][2] += a0 * b2; acc[0][3] += a0 * b3;
      acc[1][0] += a1 * b0; acc[1][1] += a1 * b1; acc[1][2] += a1 * b2; acc[1][3] += a1 * b3;
      acc[2][0] += a2 * b0; acc[2][1] += a2 * b1; acc[2][2] += a2 * b2; acc[2][3] += a2 * b3;
      acc[3][0] += a3 * b0; acc[3][1] += a3 * b1; acc[3][2] += a3 * b2; acc[3][3] += a3 * b3;
    }
#pragma unroll
    for (int r = 0; r < 4; ++r) {
      const int i = i0 + r;
      if (i < 49) {
        const int bi = (i / 7) + (i % 7);
#pragma unroll
        for (int c = 0; c < 4; ++c) {
          const int j = j0 + c;
          if (j < 49) {
            const int bj = (j / 7) + (j % 7);
            ss[i * 49 + j] = acc[r][c] * scale + sp[bi * 13 + bj];
          }
        }
      }
    }
  }
  __syncthreads();

  // ---- softmax over rows ----
  const int warp = tid >> 5, lane = tid & 31;
  for (int r = warp; r < 49; r += 4) {
    float v0 = ss[r * 49 + lane];
    float v1 = (lane + 32 < 49) ? ss[r * 49 + lane + 32] : -INFINITY;
    float m = fmaxf(v0, v1);
#pragma unroll
    for (int o = 16; o; o >>= 1) m = fmaxf(m, __shfl_xor_sync(~0u, m, o));
    float e0 = expf(v0 - m);
    float e1 = (lane + 32 < 49) ? expf(v1 - m) : 0.f;
    float sum = e0 + e1;
#pragma unroll
    for (int o = 16; o; o >>= 1) sum += __shfl_xor_sync(~0u, sum, o);
    const float inv = 1.f / sum;
    ss[r * 49 + lane] = e0 * inv;
    if (lane + 32 < 49) ss[r * 49 + lane + 32] = e1 * inv;
  }
  __syncthreads();

  // ---- PV: 104 tiles of 4x4 (13 row-blocks x 8 col-blocks), single pass ----
  if (tid < 104) {
    const int ti = tid >> 3, dj = tid & 7;
    const int i0 = ti * 4, d0 = dj * 4;
    float acc[4][4] = {};
#pragma unroll 7
    for (int l = 0; l < 49; ++l) {
      float p0 = ss[(i0 + 0) * 49 + l], p1 = ss[(i0 + 1) * 49 + l];
      float p2 = ss[(i0 + 2) * 49 + l], p3 = ss[(i0 + 3) * 49 + l];
      float v0 = sv[l][d0 + 0], v1 = sv[l][d0 + 1];
      float v2 = sv[l][d0 + 2], v3 = sv[l][d0 + 3];
      acc[0][0] += p0 * v0; acc[0][1] += p0 * v1; acc[0][2] += p0 * v2; acc[0][3] += p0 * v3;
      acc[1][0] += p1 * v0; acc[1][1] += p1 * v1; acc[1][2] += p1 * v2; acc[1][3] += p1 * v3;
      acc[2][0] += p2 * v0; acc[2][1] += p2 * v1; acc[2][2] += p2 * v2; acc[2][3] += p2 * v3;
      acc[3][0] += p3 * v0; acc[3][1] += p3 * v1; acc[3][2] += p3 * v2; acc[3][3] += p3 * v3;
    }
#pragma unroll
    for (int r = 0; r < 4; ++r) {
      const int i = i0 + r;
      if (i < 49) {
        const long grow = rowbase + (i / 7) * 56 + (i % 7);
        const size_t base = grow * 256 + head * 32 + d0;
        __nv_bfloat16 h[4], l4[4];
#pragma unroll
        for (int c = 0; c < 4; ++c) split1(acc[r][c], h[c], l4[c]);
        *reinterpret_cast<__nv_bfloat162*>(&g_ath[base]) = __nv_bfloat162(h[0], h[1]);
        *reinterpret_cast<__nv_bfloat162*>(&g_ath[base + 2]) = __nv_bfloat162(h[2], h[3]);
        *reinterpret_cast<__nv_bfloat162*>(&g_atl[base]) = __nv_bfloat162(l4[0], l4[1]);
        *reinterpret_cast<__nv_bfloat162*>(&g_atl[base + 2]) = __nv_bfloat162(l4[2], l4[3]);
      }
    }
  }
}

// ---------------------------------------------------------------------------
extern "C" void kernel_launch(void* const* d_in, const int* in_sizes, int n_in,
                              void* d_out, int out_size) {
  const float* x     = (const float*)d_in[0];
  const float* pos   = (const float*)d_in[1];
  const float* w_qkv = (const float*)d_in[2];
  const float* b_qkv = (const float*)d_in[3];
  const float* w_out = (const float*)d_in[4];
  const float* b_out = (const float*)d_in[5];
  float* out = (float*)d_out;

  float* qkv_p; __nv_bfloat16 *xh, *xl, *ath, *atl, *wqh, *wql, *woh, *wol;
  cudaGetSymbolAddress((void**)&qkv_p, g_qkv);
  cudaGetSymbolAddress((void**)&xh, g_xh);
  cudaGetSymbolAddress((void**)&xl, g_xl);
  cudaGetSymbolAddress((void**)&ath, g_ath);
  cudaGetSymbolAddress((void**)&atl, g_atl);
  cudaGetSymbolAddress((void**)&wqh, g_wqh);
  cudaGetSymbolAddress((void**)&wql, g_wql);
  cudaGetSymbolAddress((void**)&woh, g_woh);
  cudaGetSymbolAddress((void**)&wol, g_wol);

  static bool attr_set = false;
  if (!attr_set) {
    cudaFuncSetAttribute(gemm_split, cudaFuncAttributeMaxDynamicSharedMemorySize,
                         NSTAGE * STAGE_B);
    attr_set = true;
  }

  // 0) split inputs to bf16 hi/lo planes
  {
    size_t n4 = (size_t)NTOK * CDIM / 4;
    split_act<<<(unsigned)((n4 + 255) / 256), 256>>>(x, xh, xl, n4);
    split_wT<<<(CDIM * QKVD + 255) / 256, 256>>>(w_qkv, wqh, wql, CDIM, QKVD);
    split_wT<<<(CDIM * CDIM + 255) / 256, 256>>>(w_out, woh, wol, CDIM, CDIM);
  }

  // 1) qkv = x @ w_qkv + b_qkv  [200704 x 768]
  {
    dim3 g(QKVD / 128, NTOK / 128);
    gemm_split<<<g, 256, NSTAGE * STAGE_B>>>(xh, xl, wqh, wql, b_qkv, qkv_p,
                                             NTOK, QKVD, CDIM);
  }

  // 2) windowed attention -> att hi/lo planes
  {
    dim3 g(4096, 8);
    win_attn<<<g, 128>>>(pos);
  }

  // 3) out = att @ w_out + b_out  [200704 x 256]
  {
    dim3 g(CDIM / 128, NTOK / 128);
    gemm_split<<<g, 256, NSTAGE * STAGE_B>>>(ath, atl, woh, wol, b_out, out,
                                             NTOK, CDIM, CDIM);
  }
}